// round 14
// baseline (speedup 1.0000x reference)
#include <cuda_runtime.h>
#include <cuda_fp16.h>
#include <math.h>
#include <stdint.h>

// Problem constants
#define BB   512
#define TT   17
#define CC   1024
#define NH   16
#define HD   64
#define NL   12
#define MM   (BB*TT)          // 8704 tokens
#define HW28 28
#define PATCH_E 147           // 3*7*7
#define TOKB 8
#define BK   32               // gemm k-chunk (fp16)

// fused attn+ln smem: qkv fp16 (17*3072*2) + o fp32 (17*1024*4) + sc (8*17*18*4)
#define ATT_SMEM (TT*3*CC*2 + TT*CC*4 + 8*TT*18*4)

// ---------------- scratch (device globals; no allocation) ----------------
__device__ float  g_h    [MM*CC];
__device__ __half g_xn16 [MM*CC];
__device__ __half g_qkv16[(size_t)MM*3*CC];
__device__ __half g_wqkv16[(size_t)NL*3*CC*CC];
__device__ __half g_wmlp16[(size_t)NL*CC*CC];
__device__ float  g_w2[CC*PATCH_E];
__device__ float  g_b2[PATCH_E];

// ---------------- mma / ldmatrix helpers ----------------
__device__ __forceinline__ void mma_fp16(float* c, const uint32_t* a, const uint32_t* b) {
    asm volatile(
        "mma.sync.aligned.m16n8k16.row.col.f32.f16.f16.f32 "
        "{%0,%1,%2,%3}, {%4,%5,%6,%7}, {%8,%9}, {%0,%1,%2,%3};"
        : "+f"(c[0]), "+f"(c[1]), "+f"(c[2]), "+f"(c[3])
        : "r"(a[0]), "r"(a[1]), "r"(a[2]), "r"(a[3]), "r"(b[0]), "r"(b[1]));
}

__device__ __forceinline__ void ldm4(uint32_t* r, uint32_t addr) {
    asm volatile("ldmatrix.sync.aligned.m8n8.x4.shared.b16 {%0,%1,%2,%3}, [%4];"
        : "=r"(r[0]), "=r"(r[1]), "=r"(r[2]), "=r"(r[3]) : "r"(addr));
}

// ---------------- weight pack: fp32 -> fp16 ----------------
__global__ void pack_qkv_kernel(const float* __restrict__ wq, const float* __restrict__ wk,
                                const float* __restrict__ wv)
{
    const size_t per = (size_t)CC*CC/4;     // float4 per matrix
    size_t i = (size_t)blockIdx.x*blockDim.x + threadIdx.x;
    if (i >= (size_t)NL*3*per) return;
    size_t l = i / (3*per), rem = i % (3*per);
    int sel = (int)(rem / per); size_t j = rem % per;
    const float* src = (sel==0 ? wq : (sel==1 ? wk : wv)) + l*CC*CC;
    float4 v = ((const float4*)src)[j];
    __half2* dst = (__half2*)(g_wqkv16 + i*4);
    dst[0] = __floats2half2_rn(v.x, v.y);
    dst[1] = __floats2half2_rn(v.z, v.w);
}

__global__ void pack_mlp_kernel(const float* __restrict__ wm)
{
    size_t i = (size_t)blockIdx.x*blockDim.x + threadIdx.x;
    if (i >= (size_t)NL*CC*CC/4) return;
    float4 v = ((const float4*)wm)[i];
    __half2* dst = (__half2*)(g_wmlp16 + i*4);
    dst[0] = __floats2half2_rn(v.x, v.y);
    dst[1] = __floats2half2_rn(v.z, v.w);
}

// ---------------- embed: patchify + bilinear thumbnail token ----------------
__global__ void embed_kernel(const float* __restrict__ x, const float* __restrict__ cw)
{
    __shared__ float vec[TOKB][PATCH_E];
    const int tok0 = blockIdx.x * TOKB;
    const int tid  = threadIdx.x; // 256

    for (int idx = tid; idx < TOKB*PATCH_E; idx += 256) {
        int tt = idx / PATCH_E, e = idx % PATCH_E;
        int tok = tok0 + tt;
        int b = tok / TT, s = tok % TT;
        int c = e / 49, r = (e / 7) % 7, q = e % 7;
        const float* xb = x + ((size_t)(b*3 + c)) * (HW28*HW28);
        float val;
        if (s == 0) {
            int rr = 4*r + 1, qq = 4*q + 1;
            val = 0.25f * (xb[rr*HW28+qq]   + xb[rr*HW28+qq+1] +
                           xb[(rr+1)*HW28+qq] + xb[(rr+1)*HW28+qq+1]);
        } else {
            int p = s - 1; int i = p >> 2, j = p & 3;
            val = xb[(7*i + r)*HW28 + 7*j + q];
        }
        vec[tt][e] = val;
    }
    __syncthreads();

    for (int co = tid; co < CC; co += 256) {
        const float* w = cw + (size_t)co * PATCH_E;
        float acc[TOKB];
        #pragma unroll
        for (int t = 0; t < TOKB; t++) acc[t] = 0.f;
        for (int e = 0; e < PATCH_E; e++) {
            float wv = w[e];
            #pragma unroll
            for (int t = 0; t < TOKB; t++) acc[t] += vec[t][e] * wv;
        }
        #pragma unroll
        for (int t = 0; t < TOKB; t++)
            g_h[(size_t)(tok0+t)*CC + co] = acc[t];
    }
}

// ---------------- layernorm: warp per token, fp32 in fp16 out ----------------
__global__ void ln_kernel(const float* __restrict__ src, __half* __restrict__ dst,
                          const float* __restrict__ w, const float* __restrict__ b)
{
    const int wid  = threadIdx.x >> 5;
    const int lane = threadIdx.x & 31;
    const int tok  = blockIdx.x * 8 + wid;

    const float4* sp = (const float4*)(src + (size_t)tok*CC);
    float4 v[8];
    float sum = 0.f, sq = 0.f;
    #pragma unroll
    for (int j = 0; j < 8; j++) {
        v[j] = sp[lane + j*32];
        sum += v[j].x + v[j].y + v[j].z + v[j].w;
        sq  += v[j].x*v[j].x + v[j].y*v[j].y + v[j].z*v[j].z + v[j].w*v[j].w;
    }
    #pragma unroll
    for (int o = 16; o > 0; o >>= 1) {
        sum += __shfl_xor_sync(0xffffffffu, sum, o);
        sq  += __shfl_xor_sync(0xffffffffu, sq,  o);
    }
    const float m = sum * (1.f/CC);
    const float r = rsqrtf(sq * (1.f/CC) - m*m + 1e-5f);

    #pragma unroll
    for (int j = 0; j < 8; j++) {
        const int c = (lane + j*32) * 4;
        const float4 wv = *(const float4*)(w + c);
        const float4 bv = *(const float4*)(b + c);
        __half2* dp = (__half2*)(dst + (size_t)tok*CC + c);
        dp[0] = __floats2half2_rn((v[j].x - m)*r*wv.x + bv.x, (v[j].y - m)*r*wv.y + bv.y);
        dp[1] = __floats2half2_rn((v[j].z - m)*r*wv.z + bv.z, (v[j].w - m)*r*wv.w + bv.w);
    }
}

// ---------------- fp16 tensor-core GEMM (R8-proven structure, exact) ----------------
// C[m,n] = sum_k A[m,k]*Bw[n,k]; A,Bw fp16 K-major (stride CC).
// Ch != null -> write fp16 to Ch; else fp32 to Cf (+bias)(+add). Output stride N.
// 128x128 tile, BK=32, 8 warps (64x32 each), cp.async double buffer, ldmatrix.
__global__ __launch_bounds__(256, 2)
void gemm_fp16(const __half* __restrict__ A, const __half* __restrict__ Bw, int N,
               const float* __restrict__ bias, const float* __restrict__ add,
               float* __restrict__ Cf, __half* __restrict__ Ch)
{
    __shared__ __half As[2][128*BK];
    __shared__ __half Bs[2][128*BK];

    const int bm = blockIdx.y * 128;
    const int bn = blockIdx.x * 128;
    const int tid  = threadIdx.x;
    const int wid  = tid >> 5;
    const int lane = tid & 31;
    const int wm = (wid & 1) * 64;
    const int wn = (wid >> 1) * 32;
    const int g  = lane >> 2;
    const int tg = lane & 3;

    // cp.async mapping: thread -> row lr (0..127), chunk pair lcp (0 or 2); 2x16B per matrix
    const int lr  = tid >> 1;
    const int lcp = (tid & 1) * 2;
    const int sw  = (lr >> 1) & 3;
    const __half* Ag = A  + (size_t)(bm + lr)*CC + lcp*8;
    const __half* Bg = Bw + (size_t)(bn + lr)*CC + lcp*8;

    uint32_t As_addr[2], Bs_addr[2];
    As_addr[0] = (uint32_t)__cvta_generic_to_shared(&As[0][0]);
    As_addr[1] = (uint32_t)__cvta_generic_to_shared(&As[1][0]);
    Bs_addr[0] = (uint32_t)__cvta_generic_to_shared(&Bs[0][0]);
    Bs_addr[1] = (uint32_t)__cvta_generic_to_shared(&Bs[1][0]);

    auto issue = [&](int buf, int k0) {
        #pragma unroll
        for (int i = 0; i < 2; i++) {
            int phys = (lcp + i) ^ sw;
            uint32_t da = As_addr[buf] + (lr*BK + phys*8)*2;
            uint32_t db = Bs_addr[buf] + (lr*BK + phys*8)*2;
            const void* sa = (const void*)(Ag + k0 + i*8);
            const void* sb = (const void*)(Bg + k0 + i*8);
            asm volatile("cp.async.cg.shared.global [%0], [%1], 16;" :: "r"(da), "l"(sa));
            asm volatile("cp.async.cg.shared.global [%0], [%1], 16;" :: "r"(db), "l"(sb));
        }
        asm volatile("cp.async.commit_group;");
    };

    // ldmatrix lane address components
    const int rowA = wm + (lane & 15);
    const int aHi  = lane >> 4;
    const int swA  = (rowA >> 1) & 3;
    const int rowB = wn + (lane & 7) + ((lane >> 4) << 3);
    const int bHi  = (lane >> 3) & 1;
    const int swB  = (rowB >> 1) & 3;

    float acc[4][4][4];
    #pragma unroll
    for (int i = 0; i < 4; i++)
        #pragma unroll
        for (int j = 0; j < 4; j++)
            #pragma unroll
            for (int t = 0; t < 4; t++) acc[i][j][t] = 0.f;

    issue(0, 0);

    const int NCH = CC / BK; // 32
    for (int cc = 0; cc < NCH; cc++) {
        asm volatile("cp.async.wait_group 0;");
        __syncthreads();
        const int cur = cc & 1;
        if (cc + 1 < NCH) issue(1 - cur, (cc + 1) * BK);

        const uint32_t abase = As_addr[cur] + rowA * (BK*2);
        const uint32_t bbase = Bs_addr[cur] + rowB * (BK*2);

        #pragma unroll
        for (int ks = 0; ks < 2; ks++) {
            const uint32_t pa = (uint32_t)(((ks*2 + aHi) ^ swA) * 16);
            const uint32_t pb = (uint32_t)(((ks*2 + bHi) ^ swB) * 16);
            uint32_t af[4][4], bf[2][4];
            #pragma unroll
            for (int ma = 0; ma < 4; ma++)
                ldm4(af[ma], abase + ma*(16*BK*2) + pa);
            #pragma unroll
            for (int np = 0; np < 2; np++)
                ldm4(bf[np], bbase + np*(16*BK*2) + pb);
            #pragma unroll
            for (int ma = 0; ma < 4; ma++)
                #pragma unroll
                for (int na = 0; na < 4; na++)
                    mma_fp16(acc[ma][na], af[ma], &bf[na>>1][(na&1)*2]);
        }
    }

    // epilogue: c0/c1 at (row, tg*2 / +1); c2/c3 at (row+8, ...)
    #pragma unroll
    for (int ma = 0; ma < 4; ma++) {
        #pragma unroll
        for (int half = 0; half < 2; half++) {
            const int row = bm + wm + ma*16 + g + half*8;
            #pragma unroll
            for (int na = 0; na < 4; na++) {
                const int col = na*8 + tg*2;
                float ox = acc[ma][na][half*2 + 0];
                float oy = acc[ma][na][half*2 + 1];
                if (Ch) {
                    *(__half2*)(Ch + (size_t)row*N + bn + wn + col) =
                        __floats2half2_rn(ox, oy);
                } else {
                    if (bias) {
                        const float2 bb = *(const float2*)(bias + bn + wn + col);
                        ox += bb.x; oy += bb.y;
                    }
                    if (add) {
                        const float2 rr = *(const float2*)(add + (size_t)row*N + bn + wn + col);
                        ox += rr.x; oy += rr.y;
                    }
                    *(float2*)(Cf + (size_t)row*N + bn + wn + col) = make_float2(ox, oy);
                }
            }
        }
    }
}

// ---------------- fused attention + residual + ln2 ----------------
// One CTA per batch (512 CTAs, 256 threads). smem: qkv fp16 slab, o fp32, sc.
// Computes o = attn(qkv), h += o, xn = ln2(h). Numerics order-identical to the
// separate attn_kernel + ln_kernel pair.
__global__ void attn_ln_kernel(const float* __restrict__ w, const float* __restrict__ b)
{
    extern __shared__ char sbuf[];
    __half* sQKV = (__half*)sbuf;                              // TT*3*CC fp16
    float*  sO   = (float*)(sbuf + TT*3*CC*2);                 // TT*CC fp32
    float*  sScA = (float*)(sbuf + TT*3*CC*2 + TT*CC*4);       // [8][TT][18]

    const int bb   = blockIdx.x;
    const int tid  = threadIdx.x;
    const int wd   = tid >> 5;
    const int lane = tid & 31;

    // load qkv slab for this batch (contiguous 17*3072 halfs)
    {
        const float4* src = (const float4*)(g_qkv16 + (size_t)bb*TT*3*CC);
        float4* dst = (float4*)sQKV;
        for (int i = tid; i < TT*3*CC/8; i += 256) dst[i] = src[i];
    }
    __syncthreads();

    float* sc = sScA + wd*TT*18;
    #pragma unroll
    for (int hi = 0; hi < 2; hi++) {
        const int hh  = wd*2 + hi;
        const int off = hh*HD;

        // scores + softmax: lane qi owns row qi
        if (lane < TT) {
            const int qi = lane;
            const __half2* qp = (const __half2*)(sQKV + qi*3*CC + off);
            float row[TT];
            for (int kj = 0; kj <= qi; kj++) {
                const __half2* kp = (const __half2*)(sQKV + kj*3*CC + CC + off);
                float a = 0.f;
                #pragma unroll
                for (int d2 = 0; d2 < HD/2; d2++) {
                    float2 qv = __half22float2(qp[d2]);
                    float2 kv = __half22float2(kp[d2]);
                    a += qv.x*kv.x;
                    a += qv.y*kv.y;
                }
                row[kj] = a * 0.125f;
            }
            float m = -1e30f;
            for (int j = 0; j <= qi; j++) m = fmaxf(m, row[j]);
            float s = 0.f;
            for (int j = 0; j <= qi; j++) { float e2 = __expf(row[j]-m); row[j] = e2; s += e2; }
            float inv = 1.f/s;
            for (int j = 0; j <= qi; j++) sc[qi*18 + j] = row[j]*inv;
        }
        __syncwarp();

        // out: lane owns column pair c = 2*lane of this head
        {
            const int c = lane*2;
            #pragma unroll 1
            for (int t = 0; t < TT; t++) {
                float ax = 0.f, ay = 0.f;
                for (int j = 0; j <= t; j++) {
                    float p = sc[t*18 + j];
                    float2 vv = __half22float2(
                        *(const __half2*)(sQKV + j*3*CC + 2*CC + off + c));
                    ax += p*vv.x;
                    ay += p*vv.y;
                }
                sO[t*CC + off + c]   = ax;
                sO[t*CC + off + c+1] = ay;
            }
        }
        __syncwarp();
    }
    __syncthreads();

    // residual + layernorm: warp wd handles tokens wd, wd+8, ...
    for (int tok = wd; tok < TT; tok += 8) {
        float* hrow = g_h + (size_t)(bb*TT + tok)*CC;
        const float4* hp = (const float4*)hrow;
        const float4* op = (const float4*)(sO + tok*CC);
        float4 v[8];
        float sum = 0.f, sq = 0.f;
        #pragma unroll
        for (int j = 0; j < 8; j++) {
            float4 hv = hp[lane + j*32];
            float4 ov = op[lane + j*32];
            v[j].x = hv.x + ov.x; v[j].y = hv.y + ov.y;
            v[j].z = hv.z + ov.z; v[j].w = hv.w + ov.w;
            sum += v[j].x + v[j].y + v[j].z + v[j].w;
            sq  += v[j].x*v[j].x + v[j].y*v[j].y + v[j].z*v[j].z + v[j].w*v[j].w;
        }
        #pragma unroll
        for (int o = 16; o > 0; o >>= 1) {
            sum += __shfl_xor_sync(0xffffffffu, sum, o);
            sq  += __shfl_xor_sync(0xffffffffu, sq,  o);
        }
        const float m = sum * (1.f/CC);
        const float r = rsqrtf(sq * (1.f/CC) - m*m + 1e-5f);

        float4* hw = (float4*)hrow;
        __half* xrow = g_xn16 + (size_t)(bb*TT + tok)*CC;
        #pragma unroll
        for (int j = 0; j < 8; j++) {
            const int c = (lane + j*32) * 4;
            hw[lane + j*32] = v[j];
            const float4 wv = *(const float4*)(w + c);
            const float4 bv = *(const float4*)(b + c);
            __half2* dp = (__half2*)(xrow + c);
            dp[0] = __floats2half2_rn((v[j].x - m)*r*wv.x + bv.x, (v[j].y - m)*r*wv.y + bv.y);
            dp[1] = __floats2half2_rn((v[j].z - m)*r*wv.z + bv.z, (v[j].w - m)*r*wv.w + bv.w);
        }
    }
}

// ---------------- fold out_w into conv decode ----------------
__global__ void w2_kernel(const float* __restrict__ out_w, const float* __restrict__ cw)
{
    __shared__ float col[CC];
    const int e = blockIdx.x;
    const int tid = threadIdx.x;
    for (int c = tid; c < CC; c += 256) col[c] = out_w[(size_t)c*CC + e];
    __syncthreads();
    if (tid < PATCH_E) {
        float acc = 0.f;
        for (int c = 0; c < CC; c++) acc += col[c]*cw[(size_t)c*PATCH_E + tid];
        g_w2[(size_t)e*PATCH_E + tid] = acc;
    }
}

__global__ void b2_kernel(const float* __restrict__ out_b, const float* __restrict__ cw)
{
    const int n = threadIdx.x;
    if (n < PATCH_E) {
        float acc = 0.f;
        for (int c = 0; c < CC; c++) acc += out_b[c]*cw[(size_t)c*PATCH_E + n];
        g_b2[n] = acc;
    }
}

// ---------------- decode ----------------
__global__ void decode_kernel(float* __restrict__ out)
{
    __shared__ float sh[TOKB][CC];
    const int tok0 = blockIdx.x * TOKB;
    const int tid = threadIdx.x;
    const float4* src = (const float4*)(g_h + (size_t)tok0*CC);
    for (int idx = tid; idx < TOKB*CC/4; idx += 256)
        ((float4*)sh)[idx] = src[idx];
    __syncthreads();

    const int n = tid;
    if (n < PATCH_E) {
        float acc[TOKB];
        #pragma unroll
        for (int t = 0; t < TOKB; t++) acc[t] = 0.f;
        for (int e = 0; e < CC; e++) {
            float wv = g_w2[(size_t)e*PATCH_E + n];
            #pragma unroll
            for (int t = 0; t < TOKB; t++) acc[t] += sh[t][e]*wv;
        }
        float bb = g_b2[n];
        int d = n / 49, hr = (n % 49) / 7, w = n % 7;
        #pragma unroll
        for (int t = 0; t < TOKB; t++) {
            int tok = tok0 + t;
            int b = tok / TT, s = tok % TT;
            out[((size_t)(b*3 + d)*7 + hr)*119 + s*7 + w] = acc[t] + bb;
        }
    }
}

// ---------------- launch ----------------
extern "C" void kernel_launch(void* const* d_in, const int* in_sizes, int n_in,
                              void* d_out, int out_size)
{
    const float* x      = (const float*)d_in[0];
    const float* conv_w = (const float*)d_in[1];
    const float* ln1_w  = (const float*)d_in[2];
    const float* ln1_b  = (const float*)d_in[3];
    const float* wq     = (const float*)d_in[4];
    const float* wk     = (const float*)d_in[5];
    const float* wv     = (const float*)d_in[6];
    const float* ln2_w  = (const float*)d_in[7];
    const float* ln2_b  = (const float*)d_in[8];
    const float* mlp_w  = (const float*)d_in[9];
    const float* mlp_b  = (const float*)d_in[10];
    const float* out_w  = (const float*)d_in[11];
    const float* out_b  = (const float*)d_in[12];
    float* out = (float*)d_out;

    void *ph, *pxn, *pqkv, *pwqkv, *pwmlp;
    cudaGetSymbolAddress(&ph,    g_h);
    cudaGetSymbolAddress(&pxn,   g_xn16);
    cudaGetSymbolAddress(&pqkv,  g_qkv16);
    cudaGetSymbolAddress(&pwqkv, g_wqkv16);
    cudaGetSymbolAddress(&pwmlp, g_wmlp16);
    float*  h      = (float*)ph;
    __half* xn     = (__half*)pxn;
    __half* qkv16  = (__half*)pqkv;
    __half* wqkv16 = (__half*)pwqkv;
    __half* wmlp16 = (__half*)pwmlp;

    cudaFuncSetAttribute(attn_ln_kernel, cudaFuncAttributeMaxDynamicSharedMemorySize, ATT_SMEM);

    {
        size_t nq = (size_t)NL*3*CC*CC/4;
        pack_qkv_kernel<<<(unsigned)((nq + 255)/256), 256>>>(wq, wk, wv);
        size_t nm = (size_t)NL*CC*CC/4;
        pack_mlp_kernel<<<(unsigned)((nm + 255)/256), 256>>>(mlp_w);
    }

    embed_kernel<<<MM/TOKB, 256>>>(x, conv_w);

    dim3 gq(3*CC/128, MM/128);  // (24, 68)
    dim3 gm(CC/128,   MM/128);  // (8, 68)
    for (int l = 0; l < NL; l++) {
        const size_t vo = (size_t)l*CC;
        ln_kernel<<<MM/8, 256>>>(h, xn, ln1_w + vo, ln1_b + vo);
        gemm_fp16<<<gq, 256>>>(xn, wqkv16 + (size_t)l*3*CC*CC, 3*CC,
                               nullptr, nullptr, nullptr, qkv16);
        attn_ln_kernel<<<BB, 256, ATT_SMEM>>>(ln2_w + vo, ln2_b + vo);
        gemm_fp16<<<gm, 256>>>(xn, wmlp16 + (size_t)l*CC*CC, CC,
                               mlp_b + vo, h, h, nullptr);
    }

    w2_kernel<<<CC, 256>>>(out_w, conv_w);
    b2_kernel<<<1, 160>>>(out_b, conv_w);
    decode_kernel<<<MM/TOKB, 256>>>(out);
}

// round 17
// speedup vs baseline: 1.0594x; 1.0594x over previous
#include <cuda_runtime.h>
#include <cuda_fp16.h>
#include <math.h>
#include <stdint.h>

// Problem constants
#define BB   512
#define TT   17
#define CC   1024
#define NH   16
#define HD   64
#define NL   12
#define MM   (BB*TT)          // 8704 tokens
#define HW28 28
#define PATCH_E 147           // 3*7*7
#define TOKB 8
#define BK   32               // gemm k-chunk (fp16)

// ---------------- scratch (device globals; no allocation) ----------------
__device__ float  g_h    [MM*CC];
__device__ __half g_xn16 [MM*CC];
__device__ __half g_qkv16[(size_t)MM*3*CC];
__device__ __half g_wqkv16[(size_t)NL*3*CC*CC];
__device__ __half g_wmlp16[(size_t)NL*CC*CC];
__device__ float  g_w2[CC*PATCH_E];
__device__ float  g_b2[PATCH_E];

// ---------------- mma / ldmatrix helpers ----------------
__device__ __forceinline__ void mma_fp16(float* c, const uint32_t* a, const uint32_t* b) {
    asm volatile(
        "mma.sync.aligned.m16n8k16.row.col.f32.f16.f16.f32 "
        "{%0,%1,%2,%3}, {%4,%5,%6,%7}, {%8,%9}, {%0,%1,%2,%3};"
        : "+f"(c[0]), "+f"(c[1]), "+f"(c[2]), "+f"(c[3])
        : "r"(a[0]), "r"(a[1]), "r"(a[2]), "r"(a[3]), "r"(b[0]), "r"(b[1]));
}

__device__ __forceinline__ void ldm4(uint32_t* r, uint32_t addr) {
    asm volatile("ldmatrix.sync.aligned.m8n8.x4.shared.b16 {%0,%1,%2,%3}, [%4];"
        : "=r"(r[0]), "=r"(r[1]), "=r"(r[2]), "=r"(r[3]) : "r"(addr));
}

// ---------------- weight pack: fp32 -> fp16 (qkv + mlp in one launch) ----------------
__global__ void pack_kernel(const float* __restrict__ wq, const float* __restrict__ wk,
                            const float* __restrict__ wv, const float* __restrict__ wm)
{
    const size_t per  = (size_t)CC*CC/4;      // float4 per matrix
    const size_t nqkv = (size_t)NL*3*per;
    size_t i = (size_t)blockIdx.x*blockDim.x + threadIdx.x;
    if (i < nqkv) {
        size_t l = i / (3*per), rem = i % (3*per);
        int sel = (int)(rem / per); size_t j = rem % per;
        const float* src = (sel==0 ? wq : (sel==1 ? wk : wv)) + l*CC*CC;
        float4 v = ((const float4*)src)[j];
        __half2* dst = (__half2*)(g_wqkv16 + i*4);
        dst[0] = __floats2half2_rn(v.x, v.y);
        dst[1] = __floats2half2_rn(v.z, v.w);
    } else if (i < nqkv + (size_t)NL*per) {
        size_t j = i - nqkv;
        float4 v = ((const float4*)wm)[j];
        __half2* dst = (__half2*)(g_wmlp16 + j*4);
        dst[0] = __floats2half2_rn(v.x, v.y);
        dst[1] = __floats2half2_rn(v.z, v.w);
    }
}

// ---------------- embed: patchify + bilinear thumbnail token ----------------
__global__ void embed_kernel(const float* __restrict__ x, const float* __restrict__ cw)
{
    __shared__ float vec[TOKB][PATCH_E];
    const int tok0 = blockIdx.x * TOKB;
    const int tid  = threadIdx.x; // 256

    for (int idx = tid; idx < TOKB*PATCH_E; idx += 256) {
        int tt = idx / PATCH_E, e = idx % PATCH_E;
        int tok = tok0 + tt;
        int b = tok / TT, s = tok % TT;
        int c = e / 49, r = (e / 7) % 7, q = e % 7;
        const float* xb = x + ((size_t)(b*3 + c)) * (HW28*HW28);
        float val;
        if (s == 0) {
            int rr = 4*r + 1, qq = 4*q + 1;
            val = 0.25f * (xb[rr*HW28+qq]   + xb[rr*HW28+qq+1] +
                           xb[(rr+1)*HW28+qq] + xb[(rr+1)*HW28+qq+1]);
        } else {
            int p = s - 1; int i = p >> 2, j = p & 3;
            val = xb[(7*i + r)*HW28 + 7*j + q];
        }
        vec[tt][e] = val;
    }
    __syncthreads();

    for (int co = tid; co < CC; co += 256) {
        const float* w = cw + (size_t)co * PATCH_E;
        float acc[TOKB];
        #pragma unroll
        for (int t = 0; t < TOKB; t++) acc[t] = 0.f;
        for (int e = 0; e < PATCH_E; e++) {
            float wv = w[e];
            #pragma unroll
            for (int t = 0; t < TOKB; t++) acc[t] += vec[t][e] * wv;
        }
        #pragma unroll
        for (int t = 0; t < TOKB; t++)
            g_h[(size_t)(tok0+t)*CC + co] = acc[t];
    }
}

// ---------------- layernorm: warp handles 2 tokens (interleaved ILP) ----------------
__global__ void ln_kernel(const float* __restrict__ src, __half* __restrict__ dst,
                          const float* __restrict__ w, const float* __restrict__ b)
{
    const int wid  = threadIdx.x >> 5;
    const int lane = threadIdx.x & 31;
    const int tokA = blockIdx.x * 16 + wid * 2;
    const int tokB = tokA + 1;

    const float4* spA = (const float4*)(src + (size_t)tokA*CC);
    const float4* spB = (const float4*)(src + (size_t)tokB*CC);
    float4 va[8], vb[8];
    float sumA = 0.f, sqA = 0.f, sumB = 0.f, sqB = 0.f;
    #pragma unroll
    for (int j = 0; j < 8; j++) {
        va[j] = spA[lane + j*32];
        vb[j] = spB[lane + j*32];
        sumA += va[j].x + va[j].y + va[j].z + va[j].w;
        sqA  += va[j].x*va[j].x + va[j].y*va[j].y + va[j].z*va[j].z + va[j].w*va[j].w;
        sumB += vb[j].x + vb[j].y + vb[j].z + vb[j].w;
        sqB  += vb[j].x*vb[j].x + vb[j].y*vb[j].y + vb[j].z*vb[j].z + vb[j].w*vb[j].w;
    }
    #pragma unroll
    for (int o = 16; o > 0; o >>= 1) {
        sumA += __shfl_xor_sync(0xffffffffu, sumA, o);
        sqA  += __shfl_xor_sync(0xffffffffu, sqA,  o);
        sumB += __shfl_xor_sync(0xffffffffu, sumB, o);
        sqB  += __shfl_xor_sync(0xffffffffu, sqB,  o);
    }
    const float mA = sumA * (1.f/CC);
    const float rA = rsqrtf(sqA * (1.f/CC) - mA*mA + 1e-5f);
    const float mB = sumB * (1.f/CC);
    const float rB = rsqrtf(sqB * (1.f/CC) - mB*mB + 1e-5f);

    __half* dA = dst + (size_t)tokA*CC;
    __half* dB = dst + (size_t)tokB*CC;
    #pragma unroll
    for (int j = 0; j < 8; j++) {
        const int c = (lane + j*32) * 4;
        const float4 wv = *(const float4*)(w + c);
        const float4 bv = *(const float4*)(b + c);
        __half2* dpA = (__half2*)(dA + c);
        dpA[0] = __floats2half2_rn((va[j].x - mA)*rA*wv.x + bv.x, (va[j].y - mA)*rA*wv.y + bv.y);
        dpA[1] = __floats2half2_rn((va[j].z - mA)*rA*wv.z + bv.z, (va[j].w - mA)*rA*wv.w + bv.w);
        __half2* dpB = (__half2*)(dB + c);
        dpB[0] = __floats2half2_rn((vb[j].x - mB)*rB*wv.x + bv.x, (vb[j].y - mB)*rB*wv.y + bv.y);
        dpB[1] = __floats2half2_rn((vb[j].z - mB)*rB*wv.z + bv.z, (vb[j].w - mB)*rB*wv.w + bv.w);
    }
}

// ---------------- fp16 tensor-core GEMM (R8-proven structure, exact) ----------------
// C[m,n] = sum_k A[m,k]*Bw[n,k]; A,Bw fp16 K-major (stride CC).
// Ch != null -> write fp16 to Ch; else fp32 to Cf (+bias)(+add). Output stride N.
// 128x128 tile, BK=32, 8 warps (64x32 each), cp.async double buffer, ldmatrix.
__global__ __launch_bounds__(256, 2)
void gemm_fp16(const __half* __restrict__ A, const __half* __restrict__ Bw, int N,
               const float* __restrict__ bias, const float* __restrict__ add,
               float* __restrict__ Cf, __half* __restrict__ Ch)
{
    __shared__ __half As[2][128*BK];
    __shared__ __half Bs[2][128*BK];

    const int bm = blockIdx.y * 128;
    const int bn = blockIdx.x * 128;
    const int tid  = threadIdx.x;
    const int wid  = tid >> 5;
    const int lane = tid & 31;
    const int wm = (wid & 1) * 64;
    const int wn = (wid >> 1) * 32;
    const int g  = lane >> 2;
    const int tg = lane & 3;

    // cp.async mapping: thread -> row lr (0..127), chunk pair lcp (0 or 2); 2x16B per matrix
    const int lr  = tid >> 1;
    const int lcp = (tid & 1) * 2;
    const int sw  = (lr >> 1) & 3;
    const __half* Ag = A  + (size_t)(bm + lr)*CC + lcp*8;
    const __half* Bg = Bw + (size_t)(bn + lr)*CC + lcp*8;

    uint32_t As_addr[2], Bs_addr[2];
    As_addr[0] = (uint32_t)__cvta_generic_to_shared(&As[0][0]);
    As_addr[1] = (uint32_t)__cvta_generic_to_shared(&As[1][0]);
    Bs_addr[0] = (uint32_t)__cvta_generic_to_shared(&Bs[0][0]);
    Bs_addr[1] = (uint32_t)__cvta_generic_to_shared(&Bs[1][0]);

    auto issue = [&](int buf, int k0) {
        #pragma unroll
        for (int i = 0; i < 2; i++) {
            int phys = (lcp + i) ^ sw;
            uint32_t da = As_addr[buf] + (lr*BK + phys*8)*2;
            uint32_t db = Bs_addr[buf] + (lr*BK + phys*8)*2;
            const void* sa = (const void*)(Ag + k0 + i*8);
            const void* sb = (const void*)(Bg + k0 + i*8);
            asm volatile("cp.async.cg.shared.global [%0], [%1], 16;" :: "r"(da), "l"(sa));
            asm volatile("cp.async.cg.shared.global [%0], [%1], 16;" :: "r"(db), "l"(sb));
        }
        asm volatile("cp.async.commit_group;");
    };

    // ldmatrix lane address components
    const int rowA = wm + (lane & 15);
    const int aHi  = lane >> 4;
    const int swA  = (rowA >> 1) & 3;
    const int rowB = wn + (lane & 7) + ((lane >> 4) << 3);
    const int bHi  = (lane >> 3) & 1;
    const int swB  = (rowB >> 1) & 3;

    float acc[4][4][4];
    #pragma unroll
    for (int i = 0; i < 4; i++)
        #pragma unroll
        for (int j = 0; j < 4; j++)
            #pragma unroll
            for (int t = 0; t < 4; t++) acc[i][j][t] = 0.f;

    issue(0, 0);

    const int NCH = CC / BK; // 32
    for (int cc = 0; cc < NCH; cc++) {
        asm volatile("cp.async.wait_group 0;");
        __syncthreads();
        const int cur = cc & 1;
        if (cc + 1 < NCH) issue(1 - cur, (cc + 1) * BK);

        const uint32_t abase = As_addr[cur] + rowA * (BK*2);
        const uint32_t bbase = Bs_addr[cur] + rowB * (BK*2);

        #pragma unroll
        for (int ks = 0; ks < 2; ks++) {
            const uint32_t pa = (uint32_t)(((ks*2 + aHi) ^ swA) * 16);
            const uint32_t pb = (uint32_t)(((ks*2 + bHi) ^ swB) * 16);
            uint32_t af[4][4], bf[2][4];
            #pragma unroll
            for (int ma = 0; ma < 4; ma++)
                ldm4(af[ma], abase + ma*(16*BK*2) + pa);
            #pragma unroll
            for (int np = 0; np < 2; np++)
                ldm4(bf[np], bbase + np*(16*BK*2) + pb);
            #pragma unroll
            for (int ma = 0; ma < 4; ma++)
                #pragma unroll
                for (int na = 0; na < 4; na++)
                    mma_fp16(acc[ma][na], af[ma], &bf[na>>1][(na&1)*2]);
        }
    }

    // epilogue: c0/c1 at (row, tg*2 / +1); c2/c3 at (row+8, ...)
    #pragma unroll
    for (int ma = 0; ma < 4; ma++) {
        #pragma unroll
        for (int half = 0; half < 2; half++) {
            const int row = bm + wm + ma*16 + g + half*8;
            #pragma unroll
            for (int na = 0; na < 4; na++) {
                const int col = na*8 + tg*2;
                float ox = acc[ma][na][half*2 + 0];
                float oy = acc[ma][na][half*2 + 1];
                if (Ch) {
                    *(__half2*)(Ch + (size_t)row*N + bn + wn + col) =
                        __floats2half2_rn(ox, oy);
                } else {
                    if (bias) {
                        const float2 bb = *(const float2*)(bias + bn + wn + col);
                        ox += bb.x; oy += bb.y;
                    }
                    if (add) {
                        const float2 rr = *(const float2*)(add + (size_t)row*N + bn + wn + col);
                        ox += rr.x; oy += rr.y;
                    }
                    *(float2*)(Cf + (size_t)row*N + bn + wn + col) = make_float2(ox, oy);
                }
            }
        }
    }
}

// ---------------- attention: fp16 qkv in (half2 loads), h += o ----------------
__global__ void attn_kernel()
{
    __shared__ float qs[TT][65], ks[TT][65], vs[TT][65], sc[TT][20];
    const int bh = blockIdx.x;
    const int b = bh >> 4, hh = bh & 15;
    const size_t base3 = (size_t)b*TT*(3*CC) + hh*HD;
    const size_t baseh = (size_t)b*TT*CC + hh*HD;
    const int tid = threadIdx.x; // 128

    for (int idx = tid; idx < TT*(HD/2); idx += 128) {
        int t = idx / (HD/2), d2 = idx % (HD/2);
        size_t gg = base3 + (size_t)t*(3*CC) + d2*2;
        float2 q2 = __half22float2(*(const __half2*)(g_qkv16 + gg));
        float2 k2 = __half22float2(*(const __half2*)(g_qkv16 + gg + CC));
        float2 v2 = __half22float2(*(const __half2*)(g_qkv16 + gg + 2*CC));
        qs[t][d2*2] = q2.x; qs[t][d2*2+1] = q2.y;
        ks[t][d2*2] = k2.x; ks[t][d2*2+1] = k2.y;
        vs[t][d2*2] = v2.x; vs[t][d2*2+1] = v2.y;
    }
    __syncthreads();

    for (int e = tid; e < TT*TT; e += 128) {
        int qi = e / TT, kj = e % TT;
        if (kj <= qi) {
            float a = 0.f;
            #pragma unroll
            for (int d = 0; d < HD; d++) a += qs[qi][d]*ks[kj][d];
            sc[qi][kj] = a * 0.125f;
        }
    }
    __syncthreads();

    if (tid < TT) {
        int t = tid;
        float m = -1e30f;
        for (int j = 0; j <= t; j++) m = fmaxf(m, sc[t][j]);
        float s = 0.f;
        for (int j = 0; j <= t; j++) { float e2 = __expf(sc[t][j]-m); sc[t][j] = e2; s += e2; }
        float inv = 1.f/s;
        for (int j = 0; j <= t; j++) sc[t][j] *= inv;
    }
    __syncthreads();

    for (int e = tid; e < TT*HD; e += 128) {
        int t = e >> 6, d = e & 63;
        float a = 0.f;
        for (int j = 0; j <= t; j++) a += sc[t][j]*vs[j][d];
        g_h[baseh + (size_t)t*CC + d] += a;
    }
}

// ---------------- fold out_w into conv decode ----------------
__global__ void w2_kernel(const float* __restrict__ out_w, const float* __restrict__ cw)
{
    __shared__ float col[CC];
    const int e = blockIdx.x;
    const int tid = threadIdx.x;
    for (int c = tid; c < CC; c += 256) col[c] = out_w[(size_t)c*CC + e];
    __syncthreads();
    if (tid < PATCH_E) {
        float acc = 0.f;
        for (int c = 0; c < CC; c++) acc += col[c]*cw[(size_t)c*PATCH_E + tid];
        g_w2[(size_t)e*PATCH_E + tid] = acc;
    }
}

__global__ void b2_kernel(const float* __restrict__ out_b, const float* __restrict__ cw)
{
    const int n = threadIdx.x;
    if (n < PATCH_E) {
        float acc = 0.f;
        for (int c = 0; c < CC; c++) acc += out_b[c]*cw[(size_t)c*PATCH_E + n];
        g_b2[n] = acc;
    }
}

// ---------------- decode ----------------
__global__ void decode_kernel(float* __restrict__ out)
{
    __shared__ float sh[TOKB][CC];
    const int tok0 = blockIdx.x * TOKB;
    const int tid = threadIdx.x;
    const float4* src = (const float4*)(g_h + (size_t)tok0*CC);
    for (int idx = tid; idx < TOKB*CC/4; idx += 256)
        ((float4*)sh)[idx] = src[idx];
    __syncthreads();

    const int n = tid;
    if (n < PATCH_E) {
        float acc[TOKB];
        #pragma unroll
        for (int t = 0; t < TOKB; t++) acc[t] = 0.f;
        for (int e = 0; e < CC; e++) {
            float wv = g_w2[(size_t)e*PATCH_E + n];
            #pragma unroll
            for (int t = 0; t < TOKB; t++) acc[t] += sh[t][e]*wv;
        }
        float bb = g_b2[n];
        int d = n / 49, hr = (n % 49) / 7, w = n % 7;
        #pragma unroll
        for (int t = 0; t < TOKB; t++) {
            int tok = tok0 + t;
            int b = tok / TT, s = tok % TT;
            out[((size_t)(b*3 + d)*7 + hr)*119 + s*7 + w] = acc[t] + bb;
        }
    }
}

// ---------------- launch ----------------
extern "C" void kernel_launch(void* const* d_in, const int* in_sizes, int n_in,
                              void* d_out, int out_size)
{
    const float* x      = (const float*)d_in[0];
    const float* conv_w = (const float*)d_in[1];
    const float* ln1_w  = (const float*)d_in[2];
    const float* ln1_b  = (const float*)d_in[3];
    const float* wq     = (const float*)d_in[4];
    const float* wk     = (const float*)d_in[5];
    const float* wv     = (const float*)d_in[6];
    const float* ln2_w  = (const float*)d_in[7];
    const float* ln2_b  = (const float*)d_in[8];
    const float* mlp_w  = (const float*)d_in[9];
    const float* mlp_b  = (const float*)d_in[10];
    const float* out_w  = (const float*)d_in[11];
    const float* out_b  = (const float*)d_in[12];
    float* out = (float*)d_out;

    void *ph, *pxn, *pqkv, *pwqkv, *pwmlp;
    cudaGetSymbolAddress(&ph,    g_h);
    cudaGetSymbolAddress(&pxn,   g_xn16);
    cudaGetSymbolAddress(&pqkv,  g_qkv16);
    cudaGetSymbolAddress(&pwqkv, g_wqkv16);
    cudaGetSymbolAddress(&pwmlp, g_wmlp16);
    float*  h      = (float*)ph;
    __half* xn     = (__half*)pxn;
    __half* qkv16  = (__half*)pqkv;
    __half* wqkv16 = (__half*)pwqkv;
    __half* wmlp16 = (__half*)pwmlp;

    {
        size_t ntot = (size_t)NL*4*CC*CC/4;   // qkv (3) + mlp (1) matrices
        pack_kernel<<<(unsigned)((ntot + 255)/256), 256>>>(wq, wk, wv, mlp_w);
    }

    embed_kernel<<<MM/TOKB, 256>>>(x, conv_w);

    dim3 gq(3*CC/128, MM/128);  // (24, 68)
    dim3 gm(CC/128,   MM/128);  // (8, 68)
    for (int l = 0; l < NL; l++) {
        const size_t vo = (size_t)l*CC;
        ln_kernel<<<MM/16, 256>>>(h, xn, ln1_w + vo, ln1_b + vo);
        gemm_fp16<<<gq, 256>>>(xn, wqkv16 + (size_t)l*3*CC*CC, 3*CC,
                               nullptr, nullptr, nullptr, qkv16);
        attn_kernel<<<BB*NH, 128>>>();
        ln_kernel<<<MM/16, 256>>>(h, xn, ln2_w + vo, ln2_b + vo);
        gemm_fp16<<<gm, 256>>>(xn, wmlp16 + (size_t)l*CC*CC, CC,
                               mlp_b + vo, h, h, nullptr);
    }

    w2_kernel<<<CC, 256>>>(out_w, conv_w);
    b2_kernel<<<1, 160>>>(out_b, conv_w);
    decode_kernel<<<MM/TOKB, 256>>>(out);
}